// round 1
// baseline (speedup 1.0000x reference)
#include <cuda_runtime.h>
#include <math.h>

#define Bb   16
#define Tt   4096
#define Cc   512
#define Ee   256
#define NE   1024
#define NTOK (Bb*Tt)

// ---- scratch (static device memory; no runtime allocation allowed) ----
__device__ float  g_x[(size_t)NTOK * Ee];   // projected tokens [n, e], 67 MB
__device__ int    g_idx[NTOK];
__device__ float  g_enorm[NE];
__device__ int    g_hist[NE];
__device__ double g_mse;

// ---------------------------------------------------------------
// init: ||e||^2 per code, zero hist / mse
// ---------------------------------------------------------------
__global__ void k_init(const float* __restrict__ embed) {
    int c = blockIdx.x;                 // 1024 blocks, 256 threads
    float v = embed[(size_t)c * Ee + threadIdx.x];
    float s = v * v;
    __shared__ float red[8];
    for (int o = 16; o > 0; o >>= 1) s += __shfl_down_sync(0xffffffffu, s, o);
    if ((threadIdx.x & 31) == 0) red[threadIdx.x >> 5] = s;
    __syncthreads();
    if (threadIdx.x == 0) {
        float t = 0.f;
        #pragma unroll
        for (int i = 0; i < 8; i++) t += red[i];
        g_enorm[c] = t;
        g_hist[c]  = 0;
        if (c == 0) g_mse = 0.0;
    }
}

// ---------------------------------------------------------------
// projection GEMM: x[n,e] = sum_c inputs[b,c,t] * w[e,c] + bias[e]
// BM=64 tokens, BN=64 feats, BK=16, 256 threads, 4x4 per thread
// ---------------------------------------------------------------
__global__ void k_proj(const float* __restrict__ in,
                       const float* __restrict__ w,
                       const float* __restrict__ bias) {
    __shared__ float As[16][64];       // [k][token]
    __shared__ float Ws[64][17];       // [e][k]
    int tx = threadIdx.x & 15, ty = threadIdx.x >> 4;
    int n0 = blockIdx.y * 64;
    int e0 = blockIdx.x * 64;
    int b  = n0 >> 12;                 // 64 | 4096 -> whole tile in one b
    int t0 = n0 & 4095;
    const float* inb = in + (size_t)b * Cc * Tt + t0;

    float acc[4][4];
    #pragma unroll
    for (int i = 0; i < 4; i++)
        #pragma unroll
        for (int j = 0; j < 4; j++) acc[i][j] = 0.f;

    for (int kk = 0; kk < Cc; kk += 16) {
        for (int l = threadIdx.x; l < 16 * 64; l += 256) {
            int k = l >> 6, m = l & 63;
            As[k][m] = inb[(size_t)(kk + k) * Tt + m];        // coalesced over t
        }
        for (int l = threadIdx.x; l < 64 * 16; l += 256) {
            int e = l >> 4, k = l & 15;
            Ws[e][k] = w[(size_t)(e0 + e) * Cc + kk + k];     // coalesced over c
        }
        __syncthreads();
        #pragma unroll
        for (int k = 0; k < 16; k++) {
            float a[4], bv[4];
            #pragma unroll
            for (int i = 0; i < 4; i++) a[i] = As[k][ty * 4 + i];
            #pragma unroll
            for (int j = 0; j < 4; j++) bv[j] = Ws[tx * 4 + j][k];
            #pragma unroll
            for (int i = 0; i < 4; i++)
                #pragma unroll
                for (int j = 0; j < 4; j++) acc[i][j] += a[i] * bv[j];
        }
        __syncthreads();
    }
    #pragma unroll
    for (int i = 0; i < 4; i++) {
        int n = n0 + ty * 4 + i;
        #pragma unroll
        for (int j = 0; j < 4; j++) {
            int e = e0 + tx * 4 + j;
            g_x[(size_t)n * Ee + e] = acc[i][j] + bias[e];
        }
    }
}

// ---------------------------------------------------------------
// distance + argmin + histogram + mse
// per block: 32 tokens (x resident in smem), loop all 1024 codes
// 128 threads, 4x4 per thread (ty 0..7 tokens, tx 0..15 codes)
// ---------------------------------------------------------------
__global__ void k_dist(const float* __restrict__ embed) {
    __shared__ float Xs[32][Ee + 1];
    __shared__ float Es[64][17];
    __shared__ float Ens[64];
    __shared__ float redv[32][17];
    __shared__ int   redi[32][17];
    __shared__ int   sidx[32];
    __shared__ float mred[4];

    int tid = threadIdx.x;
    int tx = tid & 15, ty = tid >> 4;
    int n0 = blockIdx.x * 32;

    for (int l = tid; l < 32 * Ee; l += 128) {
        int r = l >> 8, c = l & 255;
        Xs[r][c] = g_x[(size_t)(n0 + r) * Ee + c];
    }

    float bestv[4]; int besti[4];
    #pragma unroll
    for (int i = 0; i < 4; i++) { bestv[i] = 3.0e38f; besti[i] = 0; }

    for (int c0 = 0; c0 < NE; c0 += 64) {
        __syncthreads();                      // guard Ens/Es reuse + Xs first pass
        if (tid < 64) Ens[tid] = g_enorm[c0 + tid];
        float acc[4][4];
        #pragma unroll
        for (int i = 0; i < 4; i++)
            #pragma unroll
            for (int j = 0; j < 4; j++) acc[i][j] = 0.f;

        for (int kk = 0; kk < Ee; kk += 16) {
            __syncthreads();
            for (int l = tid; l < 64 * 16; l += 128) {
                int e = l >> 4, k = l & 15;
                Es[e][k] = embed[(size_t)(c0 + e) * Ee + kk + k];
            }
            __syncthreads();
            #pragma unroll
            for (int k = 0; k < 16; k++) {
                float a[4], bv[4];
                #pragma unroll
                for (int i = 0; i < 4; i++) a[i] = Xs[ty * 4 + i][kk + k];
                #pragma unroll
                for (int j = 0; j < 4; j++) bv[j] = Es[tx * 4 + j][k];
                #pragma unroll
                for (int i = 0; i < 4; i++)
                    #pragma unroll
                    for (int j = 0; j < 4; j++) acc[i][j] += a[i] * bv[j];
            }
        }
        #pragma unroll
        for (int i = 0; i < 4; i++) {
            #pragma unroll
            for (int j = 0; j < 4; j++) {
                int c = c0 + tx * 4 + j;
                float s = Ens[tx * 4 + j] - 2.0f * acc[i][j];
                if (s < bestv[i]) { bestv[i] = s; besti[i] = c; }  // codes ascend
            }
        }
    }
    #pragma unroll
    for (int i = 0; i < 4; i++) {
        redv[ty * 4 + i][tx] = bestv[i];
        redi[ty * 4 + i][tx] = besti[i];
    }
    __syncthreads();
    if (tid < 32) {
        float bv = redv[tid][0]; int bi = redi[tid][0];
        #pragma unroll
        for (int j = 1; j < 16; j++) {
            float v = redv[tid][j]; int ii = redi[tid][j];
            if (v < bv || (v == bv && ii < bi)) { bv = v; bi = ii; }
        }
        g_idx[n0 + tid] = bi;
        sidx[tid] = bi;
        atomicAdd(&g_hist[bi], 1);
    }
    __syncthreads();
    // mse over this block's 32 tokens (x still resident in smem)
    float ms = 0.f;
    for (int l = tid; l < 32 * Ee; l += 128) {
        int r = l >> 8, c = l & 255;
        float d = embed[(size_t)sidx[r] * Ee + c] - Xs[r][c];
        ms += d * d;
    }
    for (int o = 16; o > 0; o >>= 1) ms += __shfl_down_sync(0xffffffffu, ms, o);
    if ((tid & 31) == 0) mred[tid >> 5] = ms;
    __syncthreads();
    if (tid == 0)
        atomicAdd(&g_mse, (double)(mred[0] + mred[1] + mred[2] + mred[3]));
}

// ---------------------------------------------------------------
// output: z_q_out[b,e,t] = embed[q_idx[b*T+t]][e]  (32x32 smem transpose)
// ---------------------------------------------------------------
__global__ void k_out(const float* __restrict__ embed, float* __restrict__ out) {
    __shared__ int   qs[32];
    __shared__ float sm[32][33];
    int b  = blockIdx.z;
    int e0 = blockIdx.y * 32;
    int t0 = blockIdx.x * 32;
    int tid = threadIdx.x;                     // 256
    if (tid < 32) qs[tid] = g_idx[b * Tt + t0 + tid];
    __syncthreads();
    {
        int j = tid >> 3, g = tid & 7;
        const float4* erow = (const float4*)(embed + (size_t)qs[j] * Ee + e0);
        float4 v = erow[g];
        sm[j][g * 4 + 0] = v.x; sm[j][g * 4 + 1] = v.y;
        sm[j][g * 4 + 2] = v.z; sm[j][g * 4 + 3] = v.w;
    }
    __syncthreads();
    int tl = tid & 31, eb = tid >> 5;
    #pragma unroll
    for (int r = 0; r < 4; r++) {
        int el = eb + r * 8;
        out[((size_t)b * Ee + e0 + el) * Tt + t0 + tl] = sm[tl][el];
    }
}

// ---------------------------------------------------------------
// tail scalars: loss, kldiv_r (constant), log_perplexity
// ---------------------------------------------------------------
__global__ void k_tail(float* __restrict__ out) {
    __shared__ float red[32];
    int tid = threadIdx.x;                     // 1024
    float p = (float)g_hist[tid] / 65536.0f;
    float term = -p * logf(p + 1e-10f);
    for (int o = 16; o > 0; o >>= 1) term += __shfl_down_sync(0xffffffffu, term, o);
    if ((tid & 31) == 0) red[tid >> 5] = term;
    __syncthreads();
    const size_t base = (size_t)Bb * Ee * Tt;  // 16777216
    if (tid == 0) {
        float lp = 0.f;
        #pragma unroll
        for (int i = 0; i < 32; i++) lp += red[i];
        out[base + 0]  = (float)(1.25 * (g_mse / (double)((size_t)NTOK * Ee)));
        out[base + 17] = lp;
    }
    if (tid < 16) out[base + 1 + tid] = (float)(log(1024.0) * 4096.0);
}

// ---------------------------------------------------------------
extern "C" void kernel_launch(void* const* d_in, const int* in_sizes, int n_in,
                              void* d_out, int out_size) {
    const float* inputs = (const float*)d_in[0];   // [16, 512, 4096]
    const float* proj_w = (const float*)d_in[1];   // [256, 512]
    const float* proj_b = (const float*)d_in[2];   // [256]
    const float* embed  = (const float*)d_in[3];   // [1024, 256]
    float* out = (float*)d_out;

    k_init<<<NE, 256>>>(embed);
    dim3 g1(Ee / 64, NTOK / 64);
    k_proj<<<g1, 256>>>(inputs, proj_w, proj_b);
    k_dist<<<NTOK / 32, 128>>>(embed);
    dim3 g3(Tt / 32, Ee / 32, Bb);
    k_out<<<g3, 256>>>(embed, out);
    k_tail<<<1, 1024>>>(out);
}

// round 3
// speedup vs baseline: 1.5140x; 1.5140x over previous
#include <cuda_runtime.h>
#include <math.h>

#define Bb   16
#define Tt   4096
#define Cc   512
#define Ee   256
#define NE   1024
#define NTOK (Bb*Tt)

// ---- scratch (static device memory; no runtime allocation allowed) ----
__device__ float  g_x[(size_t)NTOK * Ee];   // projected tokens [n, e], 67 MB
__device__ int    g_idx[NTOK];
__device__ float  g_enorm[NE];
__device__ int    g_hist[NE];
__device__ double g_mse;

// packed fp32x2 FMA: d.lo += a.lo*b.lo ; d.hi += a.hi*b.hi  (SASS FFMA2)
__device__ __forceinline__ void ffma2(unsigned long long& d,
                                      unsigned long long a,
                                      unsigned long long b) {
    asm("fma.rn.f32x2 %0, %1, %2, %0;" : "+l"(d) : "l"(a), "l"(b));
}
__device__ __forceinline__ float f32x2_sum(unsigned long long v) {
    unsigned int lo, hi;
    asm("mov.b64 {%0, %1}, %2;" : "=r"(lo), "=r"(hi) : "l"(v));
    return __uint_as_float(lo) + __uint_as_float(hi);
}

// ---------------------------------------------------------------
// init: ||e||^2 per code, zero hist / mse
// ---------------------------------------------------------------
__global__ void k_init(const float* __restrict__ embed) {
    int c = blockIdx.x;                 // 1024 blocks, 256 threads
    float v = embed[(size_t)c * Ee + threadIdx.x];
    float s = v * v;
    __shared__ float red[8];
    for (int o = 16; o > 0; o >>= 1) s += __shfl_down_sync(0xffffffffu, s, o);
    if ((threadIdx.x & 31) == 0) red[threadIdx.x >> 5] = s;
    __syncthreads();
    if (threadIdx.x == 0) {
        float t = 0.f;
        #pragma unroll
        for (int i = 0; i < 8; i++) t += red[i];
        g_enorm[c] = t;
        g_hist[c]  = 0;
        if (c == 0) g_mse = 0.0;
    }
}

// ---------------------------------------------------------------
// projection GEMM (f32x2-packed over the C reduction dim)
// block: 64 tokens x 128 embed-feats, 128 threads, 8x8 per thread
// x[n,e] = sum_c in[b,c,t] * w[e,c] + bias[e]
// ---------------------------------------------------------------
__global__ void __launch_bounds__(128)
k_proj(const float* __restrict__ in,
       const float* __restrict__ w,
       const float* __restrict__ bias) {
    __shared__ float As[64][34];    // [token][c-chunk], stride 34 -> conflict-free LDS.64
    __shared__ float Ws[128][34];   // [e][c-chunk]
    int tid = threadIdx.x;
    int tx = tid & 15, ty = tid >> 4;            // tx: e-dim, ty: token-dim
    int n0 = blockIdx.x * 64;
    int e0 = blockIdx.y * 128;
    int b  = n0 >> 12;
    int t0 = n0 & 4095;
    const float* inb = in + (size_t)b * Cc * Tt + t0;

    unsigned long long acc[8][8];
    #pragma unroll
    for (int i = 0; i < 8; i++)
        #pragma unroll
        for (int j = 0; j < 8; j++) acc[i][j] = 0ull;

    for (int c0 = 0; c0 < Cc; c0 += 32) {
        __syncthreads();
        // fill As: transpose gmem [c][t] -> smem [t][c] (coalesced over t)
        for (int l = tid; l < 32 * 64; l += 128) {
            int c = l >> 6, t = l & 63;
            As[t][c] = inb[(size_t)(c0 + c) * Tt + t];
        }
        // fill Ws: c-contiguous, float2
        for (int l = tid; l < 128 * 16; l += 128) {
            int e = l >> 4, c2 = l & 15;
            *(float2*)&Ws[e][c2 * 2] =
                *(const float2*)(w + (size_t)(e0 + e) * Cc + c0 + c2 * 2);
        }
        __syncthreads();
        #pragma unroll
        for (int k2 = 0; k2 < 16; k2++) {
            unsigned long long a2[8], b2[8];
            #pragma unroll
            for (int i = 0; i < 8; i++)
                a2[i] = *(const unsigned long long*)&As[i * 8 + ty][k2 * 2];
            #pragma unroll
            for (int j = 0; j < 8; j++)
                b2[j] = *(const unsigned long long*)&Ws[j * 16 + tx][k2 * 2];
            #pragma unroll
            for (int i = 0; i < 8; i++)
                #pragma unroll
                for (int j = 0; j < 8; j++) ffma2(acc[i][j], a2[i], b2[j]);
        }
    }
    #pragma unroll
    for (int i = 0; i < 8; i++) {
        int n = n0 + i * 8 + ty;
        #pragma unroll
        for (int j = 0; j < 8; j++) {
            int e = e0 + j * 16 + tx;
            g_x[(size_t)n * Ee + e] = f32x2_sum(acc[i][j]) + bias[e];
        }
    }
}

// ---------------------------------------------------------------
// distance + argmin + histogram + mse (f32x2-packed over E reduction)
// block: 64 tokens (Xs resident), loops all 1024 codes in 128-chunks
// 128 threads, 8 tokens x 8 codes per thread
// ---------------------------------------------------------------
__global__ void __launch_bounds__(128)
k_dist(const float* __restrict__ embed) {
    __shared__ float Xs[64][260];    // [token][k], stride 260: aligned fill + cf loads
    __shared__ float Es[128][34];    // [code][k-chunk]
    __shared__ float redv[64][17];
    __shared__ int   redi[64][17];
    __shared__ int   sidx[64];
    __shared__ float mred[4];

    int tid = threadIdx.x;
    int tx = tid & 15, ty = tid >> 4;            // tx: code-dim, ty: token-dim
    int n0 = blockIdx.x * 64;

    // resident x tile (float4 fill, coalesced)
    for (int l = tid; l < 64 * 64; l += 128) {
        int r = l >> 6, c4 = l & 63;
        float4 v = ((const float4*)(g_x + (size_t)(n0 + r) * Ee))[c4];
        *(float4*)&Xs[r][c4 * 4] = v;
    }

    float bestv[8]; int besti[8];
    #pragma unroll
    for (int i = 0; i < 8; i++) { bestv[i] = 3.0e38f; besti[i] = 0; }

    for (int c0 = 0; c0 < NE; c0 += 128) {
        unsigned long long acc[8][8];
        #pragma unroll
        for (int i = 0; i < 8; i++)
            #pragma unroll
            for (int j = 0; j < 8; j++) acc[i][j] = 0ull;

        for (int kk = 0; kk < Ee; kk += 32) {
            __syncthreads();
            // fill Es chunk: 128 codes x 32 k, float2 (also orders Xs fill on 1st pass)
            for (int l = tid; l < 128 * 16; l += 128) {
                int cd = l >> 4, c2 = l & 15;
                *(float2*)&Es[cd][c2 * 2] =
                    *(const float2*)(embed + (size_t)(c0 + cd) * Ee + kk + c2 * 2);
            }
            __syncthreads();
            #pragma unroll
            for (int k2 = 0; k2 < 16; k2++) {
                unsigned long long a2[8], b2[8];
                #pragma unroll
                for (int i = 0; i < 8; i++)
                    a2[i] = *(const unsigned long long*)&Xs[i * 8 + ty][kk + k2 * 2];
                #pragma unroll
                for (int j = 0; j < 8; j++)
                    b2[j] = *(const unsigned long long*)&Es[j * 16 + tx][k2 * 2];
                #pragma unroll
                for (int i = 0; i < 8; i++)
                    #pragma unroll
                    for (int j = 0; j < 8; j++) ffma2(acc[i][j], a2[i], b2[j]);
            }
        }
        // argmin update: score = ||e||^2 - 2 x.e (||x||^2 constant per token)
        #pragma unroll
        for (int j = 0; j < 8; j++) {
            int code = c0 + j * 16 + tx;         // ascending in (c0, j): first-min tiebreak
            float en = g_enorm[code];
            #pragma unroll
            for (int i = 0; i < 8; i++) {
                float s = en - 2.0f * f32x2_sum(acc[i][j]);
                if (s < bestv[i]) { bestv[i] = s; besti[i] = code; }
            }
        }
    }
    #pragma unroll
    for (int i = 0; i < 8; i++) {
        redv[i * 8 + ty][tx] = bestv[i];
        redi[i * 8 + ty][tx] = besti[i];
    }
    __syncthreads();
    if (tid < 64) {
        float bv = redv[tid][0]; int bi = redi[tid][0];
        #pragma unroll
        for (int j = 1; j < 16; j++) {
            float v = redv[tid][j]; int ii = redi[tid][j];
            if (v < bv || (v == bv && ii < bi)) { bv = v; bi = ii; }
        }
        g_idx[n0 + tid] = bi;
        sidx[tid] = bi;
        atomicAdd(&g_hist[bi], 1);
    }
    __syncthreads();
    // mse over this block's 64 tokens (x still resident in smem)
    float ms = 0.f;
    for (int l = tid; l < 64 * 64; l += 128) {
        int r = l >> 6, c4 = l & 63;
        float4 e4 = ((const float4*)(embed + (size_t)sidx[r] * Ee))[c4];
        float4 x4 = *(const float4*)&Xs[r][c4 * 4];
        float d0 = e4.x - x4.x, d1 = e4.y - x4.y;
        float d2 = e4.z - x4.z, d3 = e4.w - x4.w;
        ms += d0 * d0 + d1 * d1 + d2 * d2 + d3 * d3;
    }
    for (int o = 16; o > 0; o >>= 1) ms += __shfl_down_sync(0xffffffffu, ms, o);
    if ((tid & 31) == 0) mred[tid >> 5] = ms;
    __syncthreads();
    if (tid == 0)
        atomicAdd(&g_mse, (double)(mred[0] + mred[1] + mred[2] + mred[3]));
}

// ---------------------------------------------------------------
// output: z_q_out[b,e,t] = embed[q_idx[b*T+t]][e]  (32x32 smem transpose)
// ---------------------------------------------------------------
__global__ void k_out(const float* __restrict__ embed, float* __restrict__ out) {
    __shared__ int   qs[32];
    __shared__ float sm[32][33];
    int b  = blockIdx.z;
    int e0 = blockIdx.y * 32;
    int t0 = blockIdx.x * 32;
    int tid = threadIdx.x;                     // 256
    if (tid < 32) qs[tid] = g_idx[b * Tt + t0 + tid];
    __syncthreads();
    {
        int j = tid >> 3, g = tid & 7;
        const float4* erow = (const float4*)(embed + (size_t)qs[j] * Ee + e0);
        float4 v = erow[g];
        sm[j][g * 4 + 0] = v.x; sm[j][g * 4 + 1] = v.y;
        sm[j][g * 4 + 2] = v.z; sm[j][g * 4 + 3] = v.w;
    }
    __syncthreads();
    int tl = tid & 31, eb = tid >> 5;
    #pragma unroll
    for (int r = 0; r < 4; r++) {
        int el = eb + r * 8;
        out[((size_t)b * Ee + e0 + el) * Tt + t0 + tl] = sm[tl][el];
    }
}

// ---------------------------------------------------------------
// tail scalars: loss, kldiv_r (constant), log_perplexity
// ---------------------------------------------------------------
__global__ void k_tail(float* __restrict__ out) {
    __shared__ float red[32];
    int tid = threadIdx.x;                     // 1024
    float p = (float)g_hist[tid] / 65536.0f;
    float term = -p * logf(p + 1e-10f);
    for (int o = 16; o > 0; o >>= 1) term += __shfl_down_sync(0xffffffffu, term, o);
    if ((tid & 31) == 0) red[tid >> 5] = term;
    __syncthreads();
    const size_t base = (size_t)Bb * Ee * Tt;  // 16777216
    if (tid == 0) {
        float lp = 0.f;
        #pragma unroll
        for (int i = 0; i < 32; i++) lp += red[i];
        out[base + 0]  = (float)(1.25 * (g_mse / (double)((size_t)NTOK * Ee)));
        out[base + 17] = lp;
    }
    if (tid < 16) out[base + 1 + tid] = (float)(log(1024.0) * 4096.0);
}

// ---------------------------------------------------------------
extern "C" void kernel_launch(void* const* d_in, const int* in_sizes, int n_in,
                              void* d_out, int out_size) {
    const float* inputs = (const float*)d_in[0];   // [16, 512, 4096]
    const float* proj_w = (const float*)d_in[1];   // [256, 512]
    const float* proj_b = (const float*)d_in[2];   // [256]
    const float* embed  = (const float*)d_in[3];   // [1024, 256]
    float* out = (float*)d_out;

    k_init<<<NE, 256>>>(embed);
    dim3 g1(NTOK / 64, Ee / 128);
    k_proj<<<g1, 128>>>(inputs, proj_w, proj_b);
    k_dist<<<NTOK / 64, 128>>>(embed);
    dim3 g3(Tt / 32, Ee / 32, Bb);
    k_out<<<g3, 256>>>(embed, out);
    k_tail<<<1, 1024>>>(out);
}

// round 5
// speedup vs baseline: 2.5382x; 1.6764x over previous
#include <cuda_runtime.h>
#include <math.h>
#include <cstdint>

#define Bb   16
#define Tt   4096
#define Cc   512
#define Ee   256
#define NE   1024
#define NTOK (Bb*Tt)

// ---- scratch (static device memory) ----
// x fragments: per 64-token group: [ks(32)][k(8)][tm(4)][slot(8)] float4
//   float4 = {hi[m], hi[m+8], lo[m], lo[m+8]} for one k
__device__ __align__(16) float g_xf[(size_t)NTOK * Ee * 2];
// embed fragments: per 128-code group: [ks(32)][kp(4)][tn(16)][slot(8)] float4
//   float4 = {hi[k], hi[k+4], lo[k], lo[k+4]} for one code
__device__ __align__(16) float g_ef[(size_t)NE * Ee * 2];
__device__ float  g_enorm[NE];
__device__ float  g_xn[2][NTOK];    // per-token ||x||^2 partial (e-halves)
__device__ int    g_idx[NTOK];
__device__ int    g_hist[NE];
__device__ double g_mse;            // sum of d2_min over tokens

// ---------------- helpers ----------------
__device__ __forceinline__ uint32_t smem_u32(const void* p) {
    uint32_t a;
    asm("{ .reg .u64 t; cvta.to.shared.u64 t, %1; cvt.u32.u64 %0, t; }" : "=r"(a) : "l"(p));
    return a;
}
__device__ __forceinline__ float tf32_hi(float x) {
    uint32_t b; asm("cvt.rna.tf32.f32 %0, %1;" : "=r"(b) : "f"(x));
    return __uint_as_float(b);
}
__device__ __forceinline__ void ffma2(unsigned long long& d, unsigned long long a,
                                      unsigned long long b) {
    asm("fma.rn.f32x2 %0, %1, %2, %0;" : "+l"(d) : "l"(a), "l"(b));
}
__device__ __forceinline__ float f32x2_sum(unsigned long long v) {
    unsigned int lo, hi;
    asm("mov.b64 {%0, %1}, %2;" : "=r"(lo), "=r"(hi) : "l"(v));
    return __uint_as_float(lo) + __uint_as_float(hi);
}
__device__ __forceinline__ void mma1688(float* d, uint32_t a0, uint32_t a1,
                                        uint32_t a2, uint32_t a3,
                                        uint32_t b0, uint32_t b1) {
    asm volatile(
        "mma.sync.aligned.m16n8k8.row.col.f32.tf32.tf32.f32 "
        "{%0,%1,%2,%3}, {%4,%5,%6,%7}, {%8,%9}, {%0,%1,%2,%3};"
        : "+f"(d[0]), "+f"(d[1]), "+f"(d[2]), "+f"(d[3])
        : "r"(a0), "r"(a1), "r"(a2), "r"(a3), "r"(b0), "r"(b1));
}
__device__ __forceinline__ void cp16(uint32_t s, const void* g) {
    asm volatile("cp.async.cg.shared.global [%0], [%1], 16;" :: "r"(s), "l"(g));
}
#define CP_COMMIT() asm volatile("cp.async.commit_group;" ::: "memory")
#define CP_WAIT1()  asm volatile("cp.async.wait_group 1;" ::: "memory")
#define CP_WAIT0()  asm volatile("cp.async.wait_group 0;" ::: "memory")

// ---------------------------------------------------------------
// init: ||e||^2, embed hi/lo fragment layout, zero hist/mse
// ---------------------------------------------------------------
__global__ void k_init(const float* __restrict__ embed) {
    int c = blockIdx.x;                 // 1024 blocks, 256 threads
    int e = threadIdx.x;
    float v = embed[(size_t)c * Ee + e];
    float h = tf32_hi(v);
    float l = tf32_hi(v - h);
    int cg = c >> 7, cl = c & 127, tn = cl >> 3, n8 = cl & 7;
    int ks = e >> 3, k8 = e & 7, kp = k8 & 3, half = k8 >> 2;
    int slot = (n8 + 2 * kp) & 7;
    size_t i4 = ((((size_t)cg * 32 + ks) * 4 + kp) * 16 + tn) * 8 + slot;
    g_ef[i4 * 4 + half]     = h;
    g_ef[i4 * 4 + 2 + half] = l;

    float s = v * v;
    __shared__ float red[8];
    for (int o = 16; o > 0; o >>= 1) s += __shfl_down_sync(0xffffffffu, s, o);
    if ((e & 31) == 0) red[e >> 5] = s;
    __syncthreads();
    if (e == 0) {
        float t = 0.f;
        #pragma unroll
        for (int i = 0; i < 8; i++) t += red[i];
        g_enorm[c] = t;
        g_hist[c]  = 0;
        if (c == 0) g_mse = 0.0;
    }
}

// ---------------------------------------------------------------
// projection GEMM (scalar f32x2), epilogue stages x fragments + ||x||^2
// block: 64 tokens x 128 embed-feats, 128 threads, 8x8 per thread
// ---------------------------------------------------------------
#define PROJ_DYN 65536
__global__ void __launch_bounds__(128)
k_proj(const float* __restrict__ in,
       const float* __restrict__ w,
       const float* __restrict__ bias) {
    extern __shared__ char pdyn[];
    float* As = (float*)pdyn;                    // [64][34]
    float* Ws = (float*)(pdyn + 8704);           // [128][34]
    int tid = threadIdx.x;
    int tx = tid & 15, ty = tid >> 4;
    int n0 = blockIdx.x * 64;
    int e0 = blockIdx.y * 128;
    int b  = n0 >> 12;
    int t0 = n0 & 4095;
    const float* inb = in + (size_t)b * Cc * Tt + t0;

    unsigned long long acc[8][8];
    #pragma unroll
    for (int i = 0; i < 8; i++)
        #pragma unroll
        for (int j = 0; j < 8; j++) acc[i][j] = 0ull;

    for (int c0 = 0; c0 < Cc; c0 += 32) {
        __syncthreads();
        for (int l = tid; l < 32 * 64; l += 128) {
            int c = l >> 6, t = l & 63;
            As[t * 34 + c] = inb[(size_t)(c0 + c) * Tt + t];
        }
        for (int l = tid; l < 128 * 16; l += 128) {
            int e = l >> 4, c2 = l & 15;
            *(float2*)&Ws[e * 34 + c2 * 2] =
                *(const float2*)(w + (size_t)(e0 + e) * Cc + c0 + c2 * 2);
        }
        __syncthreads();
        #pragma unroll
        for (int k2 = 0; k2 < 16; k2++) {
            unsigned long long a2[8], b2[8];
            #pragma unroll
            for (int i = 0; i < 8; i++)
                a2[i] = *(const unsigned long long*)&As[(i * 8 + ty) * 34 + k2 * 2];
            #pragma unroll
            for (int j = 0; j < 8; j++)
                b2[j] = *(const unsigned long long*)&Ws[(j * 16 + tx) * 34 + k2 * 2];
            #pragma unroll
            for (int i = 0; i < 8; i++)
                #pragma unroll
                for (int j = 0; j < 8; j++) ffma2(acc[i][j], a2[i], b2[j]);
        }
    }
    __syncthreads();                 // As/Ws dead; reuse pdyn as fragment stage
    float* stage = (float*)pdyn;     // 16384 floats = 64KB

    float xn[8];
    #pragma unroll
    for (int i = 0; i < 8; i++) xn[i] = 0.f;

    #pragma unroll
    for (int i = 0; i < 8; i++) {
        int nl = i * 8 + ty;                        // token local 0..63
        int tm = nl >> 4, rr = nl & 15;
        int r  = rr & 7, comp = rr >> 3;            // comp: 0 -> m, 1 -> m+8
        #pragma unroll
        for (int j = 0; j < 8; j++) {
            int el = j * 16 + tx;                   // 0..127
            int e  = e0 + el;
            float xv = f32x2_sum(acc[i][j]) + bias[e];
            xn[i] += xv * xv;
            float h = tf32_hi(xv);
            float l = tf32_hi(xv - h);
            int ksl = el >> 3, k8 = el & 7;
            int slot = (r + 2 * (k8 & 3)) & 7;
            int idx = (((ksl * 8 + k8) * 32 + tm * 8 + slot) << 2);
            stage[idx + comp]     = h;
            stage[idx + 2 + comp] = l;
        }
    }
    // ||x||^2 partial: reduce over the 16 tx-lanes holding the same token
    #pragma unroll
    for (int i = 0; i < 8; i++) {
        float s = xn[i];
        for (int o = 8; o > 0; o >>= 1) s += __shfl_down_sync(0xffffffffu, s, o, 16);
        if (tx == 0) g_xn[blockIdx.y][n0 + i * 8 + ty] = s;
    }
    __syncthreads();
    // stream stage -> g_xf (contiguous region for this block)
    int g = n0 >> 6;
    float4* dst = (float4*)g_xf + (size_t)g * 8192 + (size_t)(e0 >> 3) * 256;
    const float4* src = (const float4*)stage;
    for (int i = tid; i < 4096; i += 128) dst[i] = src[i];
}

// ---------------------------------------------------------------
// distance via mma.sync tf32x3: CTA = 64 tokens x all 1024 codes
// A resident (128KB), B double-buffered cp.async (2x32KB)
// 8 warps: 2 (m) x 4 (n); warp tile 32 tokens x 32 codes
// ---------------------------------------------------------------
#define DIST_DYN 202752
__global__ void __launch_bounds__(256, 1)
k_dist() {
    extern __shared__ char dyn[];
    float4* smA  = (float4*)dyn;                        // 8192 f4
    float4* smB0 = (float4*)(dyn + 131072);             // 2048 f4
    float4* smB1 = (float4*)(dyn + 163840);             // 2048 f4
    float*  s_en = (float*)(dyn + 196608);              // 1024 f
    float*  redv = (float*)(dyn + 200704);              // 64*4
    int*    redi = (int*)(dyn + 201728);                // 64*4
    __shared__ float lred[2];

    int tid  = threadIdx.x;
    int wid  = tid >> 5, lane = tid & 31;
    int wm   = wid >> 2, wn = wid & 3;
    int q    = lane >> 2, kq = lane & 3;
    int slot = (q + 2 * kq) & 7;
    int g    = blockIdx.x;                              // token group (64 tokens)
    uint32_t smAu  = smem_u32(smA);
    uint32_t smBu[2] = { smem_u32(smB0), smem_u32(smB1) };

    // A fill (cp.async), group g contiguous
    {
        const char* src = (const char*)((const float4*)g_xf + (size_t)g * 8192);
        for (int i = tid; i < 8192; i += 256)
            cp16(smAu + (uint32_t)i * 16, src + (size_t)i * 16);
        CP_COMMIT();
    }
    for (int i = tid; i < 1024; i += 256) s_en[i] = g_enorm[i];

    // issue B chunk gc: cg = gc>>3, ch = gc&7 (4 ks per chunk)
    #define ISSUE(gc) do {                                                        \
        int _cg = (gc) >> 3, _ch = (gc) & 7;                                      \
        const char* _s = (const char*)((const float4*)g_ef +                      \
                          (size_t)_cg * 16384 + (size_t)_ch * 2048);              \
        uint32_t _d = smBu[(gc) & 1];                                             \
        for (int i = tid; i < 2048; i += 256)                                     \
            cp16(_d + (uint32_t)i * 16, _s + (size_t)i * 16);                     \
        CP_COMMIT();                                                              \
    } while (0)

    ISSUE(0);

    float acc[2][4][4];
    #pragma unroll
    for (int a = 0; a < 2; a++)
        #pragma unroll
        for (int b = 0; b < 4; b++)
            #pragma unroll
            for (int c = 0; c < 4; c++) acc[a][b][c] = 0.f;
    float bestv[4]; int besti[4];
    #pragma unroll
    for (int s = 0; s < 4; s++) { bestv[s] = 3.0e38f; besti[s] = 0; }

    for (int gc = 0; gc < 64; gc++) {
        if (gc + 1 < 64) { ISSUE(gc + 1); CP_WAIT1(); } else { CP_WAIT0(); }
        __syncthreads();
        const float4* B4 = (gc & 1) ? smB1 : smB0;
        int ch = gc & 7;
        #pragma unroll
        for (int ksl = 0; ksl < 4; ksl++) {
            int ks = ch * 4 + ksl;
            // A fragments (hi+lo) for 2 m-tiles
            float4 aA[2], aB[2];
            #pragma unroll
            for (int tm2 = 0; tm2 < 2; tm2++) {
                int tmg = wm * 2 + tm2;
                aA[tm2] = smA[(ks * 8 + kq) * 32 + tmg * 8 + slot];
                aB[tm2] = smA[(ks * 8 + kq + 4) * 32 + tmg * 8 + slot];
            }
            // B fragments (hi+lo) for 4 n-tiles
            float4 bf[4];
            #pragma unroll
            for (int tn4 = 0; tn4 < 4; tn4++) {
                int tng = wn * 4 + tn4;
                bf[tn4] = B4[((ksl * 4 + kq) * 16 + tng) * 8 + slot];
            }
            #pragma unroll
            for (int tm2 = 0; tm2 < 2; tm2++) {
                uint32_t ah0 = __float_as_uint(aA[tm2].x), ah1 = __float_as_uint(aA[tm2].y);
                uint32_t ah2 = __float_as_uint(aB[tm2].x), ah3 = __float_as_uint(aB[tm2].y);
                uint32_t al0 = __float_as_uint(aA[tm2].z), al1 = __float_as_uint(aA[tm2].w);
                uint32_t al2 = __float_as_uint(aB[tm2].z), al3 = __float_as_uint(aB[tm2].w);
                #pragma unroll
                for (int tn4 = 0; tn4 < 4; tn4++) {
                    uint32_t bh0 = __float_as_uint(bf[tn4].x), bh1 = __float_as_uint(bf[tn4].y);
                    uint32_t bl0 = __float_as_uint(bf[tn4].z), bl1 = __float_as_uint(bf[tn4].w);
                    mma1688(acc[tm2][tn4], ah0, ah1, ah2, ah3, bh0, bh1);
                    mma1688(acc[tm2][tn4], ah0, ah1, ah2, ah3, bl0, bl1);
                    mma1688(acc[tm2][tn4], al0, al1, al2, al3, bh0, bh1);
                }
            }
        }
        if ((gc & 7) == 7) {
            int cg = gc >> 3;
            #pragma unroll
            for (int tm2 = 0; tm2 < 2; tm2++) {
                #pragma unroll
                for (int tn4 = 0; tn4 < 4; tn4++) {
                    int nb = cg * 128 + wn * 32 + tn4 * 8 + 2 * kq;
                    float e0v = s_en[nb], e1v = s_en[nb + 1];
                    float s00 = fmaf(-2.0f, acc[tm2][tn4][0], e0v);
                    float s01 = fmaf(-2.0f, acc[tm2][tn4][1], e1v);
                    float s10 = fmaf(-2.0f, acc[tm2][tn4][2], e0v);
                    float s11 = fmaf(-2.0f, acc[tm2][tn4][3], e1v);
                    int s0 = tm2 * 2, s1 = tm2 * 2 + 1;
                    if (s00 < bestv[s0]) { bestv[s0] = s00; besti[s0] = nb; }
                    if (s01 < bestv[s0]) { bestv[s0] = s01; besti[s0] = nb + 1; }
                    if (s10 < bestv[s1]) { bestv[s1] = s10; besti[s1] = nb; }
                    if (s11 < bestv[s1]) { bestv[s1] = s11; besti[s1] = nb + 1; }
                    acc[tm2][tn4][0] = 0.f; acc[tm2][tn4][1] = 0.f;
                    acc[tm2][tn4][2] = 0.f; acc[tm2][tn4][3] = 0.f;
                }
            }
        }
        __syncthreads();
    }
    // quad reduce (lanes of a quad share rows, differ in codes)
    #pragma unroll
    for (int s = 0; s < 4; s++) {
        float v = bestv[s]; int bi = besti[s];
        #pragma unroll
        for (int off = 1; off <= 2; off <<= 1) {
            float ov = __shfl_xor_sync(0xffffffffu, v, off);
            int   oi = __shfl_xor_sync(0xffffffffu, bi, off);
            if (ov < v || (ov == v && oi < bi)) { v = ov; bi = oi; }
        }
        if ((lane & 3) == 0) {
            int row = wm * 32 + (s >> 1) * 16 + (s & 1) * 8 + q;
            redv[row * 4 + wn] = v;
            redi[row * 4 + wn] = bi;
        }
    }
    __syncthreads();
    float myd2 = 0.f;
    if (tid < 64) {
        float v = redv[tid * 4]; int bi = redi[tid * 4];
        #pragma unroll
        for (int j = 1; j < 4; j++) {
            float ov = redv[tid * 4 + j]; int oi = redi[tid * 4 + j];
            if (ov < v || (ov == v && oi < bi)) { v = ov; bi = oi; }
        }
        int n = g * 64 + tid;
        g_idx[n] = bi;
        atomicAdd(&g_hist[bi], 1);
        myd2 = g_xn[0][n] + g_xn[1][n] + v;   // ||x||^2 + (||e||^2 - 2x.e)
    }
    for (int o = 16; o > 0; o >>= 1) myd2 += __shfl_down_sync(0xffffffffu, myd2, o);
    if (lane == 0 && wid < 2) lred[wid] = myd2;
    __syncthreads();
    if (tid == 0) atomicAdd(&g_mse, (double)(lred[0] + lred[1]));
}

// ---------------------------------------------------------------
// output: z_q_out[b,e,t] = embed[q_idx[b*T+t]][e]  (32x32 transpose)
// ---------------------------------------------------------------
__global__ void k_out(const float* __restrict__ embed, float* __restrict__ out) {
    __shared__ int   qs[32];
    __shared__ float sm[32][33];
    int b  = blockIdx.z;
    int e0 = blockIdx.y * 32;
    int t0 = blockIdx.x * 32;
    int tid = threadIdx.x;
    if (tid < 32) qs[tid] = g_idx[b * Tt + t0 + tid];
    __syncthreads();
    {
        int j = tid >> 3, gg = tid & 7;
        const float4* erow = (const float4*)(embed + (size_t)qs[j] * Ee + e0);
        float4 v = erow[gg];
        sm[j][gg * 4 + 0] = v.x; sm[j][gg * 4 + 1] = v.y;
        sm[j][gg * 4 + 2] = v.z; sm[j][gg * 4 + 3] = v.w;
    }
    __syncthreads();
    int tl = tid & 31, eb = tid >> 5;
    #pragma unroll
    for (int r = 0; r < 4; r++) {
        int el = eb + r * 8;
        out[((size_t)b * Ee + e0 + el) * Tt + t0 + tl] = sm[tl][el];
    }
}

// ---------------------------------------------------------------
// tail scalars
// ---------------------------------------------------------------
__global__ void k_tail(float* __restrict__ out) {
    __shared__ float red[32];
    int tid = threadIdx.x;                     // 1024
    float p = (float)g_hist[tid] / 65536.0f;
    float term = -p * logf(p + 1e-10f);
    for (int o = 16; o > 0; o >>= 1) term += __shfl_down_sync(0xffffffffu, term, o);
    if ((tid & 31) == 0) red[tid >> 5] = term;
    __syncthreads();
    const size_t base = (size_t)Bb * Ee * Tt;
    if (tid == 0) {
        float lp = 0.f;
        #pragma unroll
        for (int i = 0; i < 32; i++) lp += red[i];
        out[base + 0]  = (float)(1.25 * (g_mse / (double)((size_t)NTOK * Ee)));
        out[base + 17] = lp;
    }
    if (tid < 16) out[base + 1 + tid] = (float)(log(1024.0) * 4096.0);
}

// ---------------------------------------------------------------
extern "C" void kernel_launch(void* const* d_in, const int* in_sizes, int n_in,
                              void* d_out, int out_size) {
    const float* inputs = (const float*)d_in[0];   // [16, 512, 4096]
    const float* proj_w = (const float*)d_in[1];   // [256, 512]
    const float* proj_b = (const float*)d_in[2];   // [256]
    const float* embed  = (const float*)d_in[3];   // [1024, 256]
    float* out = (float*)d_out;

    cudaFuncSetAttribute(k_proj, cudaFuncAttributeMaxDynamicSharedMemorySize, PROJ_DYN);
    cudaFuncSetAttribute(k_dist, cudaFuncAttributeMaxDynamicSharedMemorySize, DIST_DYN);

    k_init<<<NE, 256>>>(embed);
    dim3 g1(NTOK / 64, 2);
    k_proj<<<g1, 128, PROJ_DYN>>>(inputs, proj_w, proj_b);
    k_dist<<<NTOK / 64, 256, DIST_DYN>>>();
    dim3 g3(Tt / 32, Ee / 32, Bb);
    k_out<<<g3, 256>>>(embed, out);
    k_tail<<<1, 1024>>>(out);
}

// round 6
// speedup vs baseline: 2.8592x; 1.1265x over previous
#include <cuda_runtime.h>
#include <math.h>
#include <cstdint>

#define Bb   16
#define Tt   4096
#define Cc   512
#define Ee   256
#define NE   1024
#define NTOK (Bb*Tt)

// ---- scratch (static device memory) ----
// x fragments: per 64-token group: [ks(32)][k(8)][tm(4)][slot(8)] float4
//   float4 = {hi[m], hi[m+8], lo[m], lo[m+8]} for one k(=e)
__device__ __align__(16) float g_xf[(size_t)NTOK * Ee * 2];
// embed fragments: per 128-code group: [ks(32)][kp(4)][tn(16)][slot(8)] float4
__device__ __align__(16) float g_ef[(size_t)NE * Ee * 2];
// proj-weight fragments: [ks(64)][kp(4)][tn(32)][slot(8)] float4
__device__ __align__(16) float g_wf[(size_t)Ee * Cc * 2];
__device__ float  g_enorm[NE];
__device__ float  g_xn[NTOK];       // per-token ||x||^2
__device__ int    g_idx[NTOK];
__device__ int    g_hist[NE];
__device__ double g_mse;            // sum of d2_min over tokens

// ---------------- helpers ----------------
__device__ __forceinline__ uint32_t smem_u32(const void* p) {
    uint32_t a;
    asm("{ .reg .u64 t; cvta.to.shared.u64 t, %1; cvt.u32.u64 %0, t; }" : "=r"(a) : "l"(p));
    return a;
}
__device__ __forceinline__ float tf32_hi(float x) {
    uint32_t b; asm("cvt.rna.tf32.f32 %0, %1;" : "=r"(b) : "f"(x));
    return __uint_as_float(b);
}
__device__ __forceinline__ void mma1688(float* d, uint32_t a0, uint32_t a1,
                                        uint32_t a2, uint32_t a3,
                                        uint32_t b0, uint32_t b1) {
    asm volatile(
        "mma.sync.aligned.m16n8k8.row.col.f32.tf32.tf32.f32 "
        "{%0,%1,%2,%3}, {%4,%5,%6,%7}, {%8,%9}, {%0,%1,%2,%3};"
        : "+f"(d[0]), "+f"(d[1]), "+f"(d[2]), "+f"(d[3])
        : "r"(a0), "r"(a1), "r"(a2), "r"(a3), "r"(b0), "r"(b1));
}
__device__ __forceinline__ void cp16(uint32_t s, const void* g) {
    asm volatile("cp.async.cg.shared.global [%0], [%1], 16;" :: "r"(s), "l"(g));
}
#define CP_COMMIT() asm volatile("cp.async.commit_group;" ::: "memory")
#define CP_WAIT1()  asm volatile("cp.async.wait_group 1;" ::: "memory")
#define CP_WAIT0()  asm volatile("cp.async.wait_group 0;" ::: "memory")

// ---------------------------------------------------------------
// init: ||e||^2, embed hi/lo fragment layout, zero hist/mse
// ---------------------------------------------------------------
__global__ void k_init(const float* __restrict__ embed) {
    int c = blockIdx.x;                 // 1024 blocks, 256 threads
    int e = threadIdx.x;
    float v = embed[(size_t)c * Ee + e];
    float h = tf32_hi(v);
    float l = tf32_hi(v - h);
    int cg = c >> 7, cl = c & 127, tn = cl >> 3, n8 = cl & 7;
    int ks = e >> 3, k8 = e & 7, kp = k8 & 3, half = k8 >> 2;
    int slot = (n8 + 2 * kp) & 7;
    size_t i4 = ((((size_t)cg * 32 + ks) * 4 + kp) * 16 + tn) * 8 + slot;
    g_ef[i4 * 4 + half]     = h;
    g_ef[i4 * 4 + 2 + half] = l;

    float s = v * v;
    __shared__ float red[8];
    for (int o = 16; o > 0; o >>= 1) s += __shfl_down_sync(0xffffffffu, s, o);
    if ((e & 31) == 0) red[e >> 5] = s;
    __syncthreads();
    if (e == 0) {
        float t = 0.f;
        #pragma unroll
        for (int i = 0; i < 8; i++) t += red[i];
        g_enorm[c] = t;
        g_hist[c]  = 0;
        if (c == 0) g_mse = 0.0;
    }
}

// ---------------------------------------------------------------
// winit: proj weight hi/lo fragments (B operand layout, N=256 e's)
// grid 512 (c), block 256 (e)
// ---------------------------------------------------------------
__global__ void k_winit(const float* __restrict__ w) {
    int c = blockIdx.x;                 // 0..511
    int e = threadIdx.x;                // 0..255
    float v = w[(size_t)e * Cc + c];
    float h = tf32_hi(v);
    float l = tf32_hi(v - h);
    int ks = c >> 3, k8 = c & 7, kp = k8 & 3, half = k8 >> 2;
    int tn = e >> 3, n8 = e & 7;
    int slot = (n8 + 2 * kp) & 7;
    size_t i4 = (((size_t)ks * 4 + kp) * 32 + tn) * 8 + slot;
    g_wf[i4 * 4 + half]     = h;
    g_wf[i4 * 4 + 2 + half] = l;
}

// ---------------------------------------------------------------
// projection via mma.sync tf32x3: CTA = 128 tokens x 256 feats
// A transposed+split on the fly; W frags streamed via cp.async
// 8 warps = 2(m) x 4(n); warp tile 64 tokens x 64 feats
// epilogue: bias, ||x||^2, write x fragments in k_dist A-layout
// ---------------------------------------------------------------
#define PROJ_DYN (32768 + 2 * 65536)
__global__ void __launch_bounds__(256, 1)
k_proj(const float* __restrict__ in, const float* __restrict__ bias) {
    extern __shared__ char dyn[];
    float4* fragA = (float4*)dyn;                                   // 2048 f4
    float4* smB0  = (float4*)(dyn + 32768);                         // 4096 f4
    float4* smB1  = (float4*)(dyn + 98304);                         // 4096 f4
    __shared__ float sBias[256];
    __shared__ float sXn[128];

    int tid  = threadIdx.x;
    int lane = tid & 31, wid = tid >> 5;
    int wm   = wid >> 2, wn = wid & 3;
    int q    = lane >> 2, kq = lane & 3;
    int S    = (q + 2 * kq) & 7;
    int n0   = blockIdx.x * 128;
    int b    = n0 >> 12, t0 = n0 & 4095;
    const float* inb = in + (size_t)b * Cc * Tt + t0;
    uint32_t smBu[2] = { smem_u32(smB0), smem_u32(smB1) };

    sBias[tid & 255] = bias[tid & 255];
    if (tid < 128) sXn[tid] = 0.f;

    #define ISSUE_W(ch) do {                                                     \
        const char* _s = (const char*)((const float4*)g_wf + (size_t)(ch)*4096); \
        uint32_t _d = smBu[(ch) & 1];                                            \
        for (int i = tid; i < 4096; i += 256)                                    \
            cp16(_d + (uint32_t)i * 16, _s + (size_t)i * 16);                    \
        CP_COMMIT();                                                             \
    } while (0)

    ISSUE_W(0);
    ISSUE_W(1);

    float acc[4][8][4];
    #pragma unroll
    for (int a = 0; a < 4; a++)
        #pragma unroll
        for (int bb = 0; bb < 8; bb++)
            #pragma unroll
            for (int cix = 0; cix < 4; cix++) acc[a][bb][cix] = 0.f;

    for (int ch = 0; ch < 16; ch++) {
        // ---- A fill: LDG token pair, tf32 split, fragment STS ----
        {
            float v0[8], v1[8];
            #pragma unroll
            for (int it = 0; it < 8; it++) {
                int item = it * 256 + tid;
                int r = item & 7, tm = (item >> 3) & 7, c = item >> 6;
                const float* p = inb + (size_t)(ch * 32 + c) * Tt + tm * 16 + r;
                v0[it] = p[0];
                v1[it] = p[8];
            }
            #pragma unroll
            for (int it = 0; it < 8; it++) {
                int item = it * 256 + tid;
                int r = item & 7, tm = (item >> 3) & 7, c = item >> 6;
                int k8 = c & 7, ksl = c >> 3, kp = k8 & 3, sl = (r + 2 * kp) & 7;
                float h0 = tf32_hi(v0[it]), l0 = tf32_hi(v0[it] - h0);
                float h1 = tf32_hi(v1[it]), l1 = tf32_hi(v1[it] - h1);
                fragA[((ksl * 8 + k8) * 8 + tm) * 8 + sl] = make_float4(h0, h1, l0, l1);
            }
        }
        if (ch < 15) CP_WAIT1(); else CP_WAIT0();
        __syncthreads();
        const float4* B4 = (ch & 1) ? smB1 : smB0;
        #pragma unroll
        for (int ksl = 0; ksl < 4; ksl++) {
            float4 aA[4], aB[4];
            #pragma unroll
            for (int mt = 0; mt < 4; mt++) {
                int tmg = wm * 4 + mt;
                aA[mt] = fragA[((ksl * 8 + kq) * 8 + tmg) * 8 + S];
                aB[mt] = fragA[((ksl * 8 + kq + 4) * 8 + tmg) * 8 + S];
            }
            #pragma unroll
            for (int nt = 0; nt < 8; nt++) {
                float4 bf = B4[((ksl * 4 + kq) * 32 + wn * 8 + nt) * 8 + S];
                uint32_t bh0 = __float_as_uint(bf.x), bh1 = __float_as_uint(bf.y);
                uint32_t bl0 = __float_as_uint(bf.z), bl1 = __float_as_uint(bf.w);
                #pragma unroll
                for (int mt = 0; mt < 4; mt++) {
                    uint32_t ah0 = __float_as_uint(aA[mt].x), ah1 = __float_as_uint(aA[mt].y);
                    uint32_t ah2 = __float_as_uint(aB[mt].x), ah3 = __float_as_uint(aB[mt].y);
                    uint32_t al0 = __float_as_uint(aA[mt].z), al1 = __float_as_uint(aA[mt].w);
                    uint32_t al2 = __float_as_uint(aB[mt].z), al3 = __float_as_uint(aB[mt].w);
                    mma1688(acc[mt][nt], ah0, ah1, ah2, ah3, bh0, bh1);
                    mma1688(acc[mt][nt], ah0, ah1, ah2, ah3, bl0, bl1);
                    mma1688(acc[mt][nt], al0, al1, al2, al3, bh0, bh1);
                }
            }
        }
        __syncthreads();
        if (ch + 2 < 16) ISSUE_W(ch + 2);
    }

    // ---- epilogue: bias, x fragments (k_dist A layout), ||x||^2 ----
    int g = (n0 >> 6) + wm;                       // 64-token group per wm
    float4* xf4 = (float4*)g_xf + (size_t)g * 8192;
    float xnq[4], xnq8[4];
    #pragma unroll
    for (int mt = 0; mt < 4; mt++) { xnq[mt] = 0.f; xnq8[mt] = 0.f; }

    #pragma unroll
    for (int mt = 0; mt < 4; mt++) {
        #pragma unroll
        for (int nt = 0; nt < 8; nt++) {
            int e = wn * 64 + nt * 8 + 2 * kq;
            float x0 = acc[mt][nt][0] + sBias[e];
            float x1 = acc[mt][nt][1] + sBias[e + 1];
            float x2 = acc[mt][nt][2] + sBias[e];
            float x3 = acc[mt][nt][3] + sBias[e + 1];
            xnq[mt]  += x0 * x0 + x1 * x1;
            xnq8[mt] += x2 * x2 + x3 * x3;
            {
                int k8 = e & 7, ks = e >> 3, kp = k8 & 3, sl = (q + 2 * kp) & 7;
                float h0 = tf32_hi(x0), h2 = tf32_hi(x2);
                xf4[((ks * 8 + k8) * 4 + mt) * 8 + sl] =
                    make_float4(h0, h2, tf32_hi(x0 - h0), tf32_hi(x2 - h2));
            }
            {
                int e1 = e + 1;
                int k8 = e1 & 7, ks = e1 >> 3, kp = k8 & 3, sl = (q + 2 * kp) & 7;
                float h1 = tf32_hi(x1), h3 = tf32_hi(x3);
                xf4[((ks * 8 + k8) * 4 + mt) * 8 + sl] =
                    make_float4(h1, h3, tf32_hi(x1 - h1), tf32_hi(x3 - h3));
            }
        }
    }
    // reduce ||x||^2 over kq lanes, then across wn warps via smem atomics
    #pragma unroll
    for (int mt = 0; mt < 4; mt++) {
        float a = xnq[mt], b2 = xnq8[mt];
        a  += __shfl_xor_sync(0xffffffffu, a, 1);
        a  += __shfl_xor_sync(0xffffffffu, a, 2);
        b2 += __shfl_xor_sync(0xffffffffu, b2, 1);
        b2 += __shfl_xor_sync(0xffffffffu, b2, 2);
        if (kq == 0) {
            int tl = wm * 64 + mt * 16 + q;
            atomicAdd(&sXn[tl], a);
            atomicAdd(&sXn[tl + 8], b2);
        }
    }
    __syncthreads();
    if (tid < 128) g_xn[n0 + tid] = sXn[tid];
}

// ---------------------------------------------------------------
// distance via mma.sync tf32x3: CTA = 64 tokens x all 1024 codes
// A resident (128KB), B double-buffered cp.async (2x32KB)
// ---------------------------------------------------------------
#define DIST_DYN 202752
__global__ void __launch_bounds__(256, 1)
k_dist() {
    extern __shared__ char dyn[];
    float4* smA  = (float4*)dyn;                        // 8192 f4
    float4* smB0 = (float4*)(dyn + 131072);             // 2048 f4
    float4* smB1 = (float4*)(dyn + 163840);             // 2048 f4
    float*  s_en = (float*)(dyn + 196608);              // 1024 f
    float*  redv = (float*)(dyn + 200704);              // 64*4
    int*    redi = (int*)(dyn + 201728);                // 64*4
    __shared__ float lred[2];

    int tid  = threadIdx.x;
    int wid  = tid >> 5, lane = tid & 31;
    int wm   = wid >> 2, wn = wid & 3;
    int q    = lane >> 2, kq = lane & 3;
    int slot = (q + 2 * kq) & 7;
    int g    = blockIdx.x;                              // token group (64 tokens)
    uint32_t smAu  = smem_u32(smA);
    uint32_t smBu[2] = { smem_u32(smB0), smem_u32(smB1) };

    {
        const char* src = (const char*)((const float4*)g_xf + (size_t)g * 8192);
        for (int i = tid; i < 8192; i += 256)
            cp16(smAu + (uint32_t)i * 16, src + (size_t)i * 16);
        CP_COMMIT();
    }
    for (int i = tid; i < 1024; i += 256) s_en[i] = g_enorm[i];

    #define ISSUE(gc) do {                                                        \
        int _cg = (gc) >> 3, _ch = (gc) & 7;                                      \
        const char* _s = (const char*)((const float4*)g_ef +                      \
                          (size_t)_cg * 16384 + (size_t)_ch * 2048);              \
        uint32_t _d = smBu[(gc) & 1];                                             \
        for (int i = tid; i < 2048; i += 256)                                     \
            cp16(_d + (uint32_t)i * 16, _s + (size_t)i * 16);                     \
        CP_COMMIT();                                                              \
    } while (0)

    ISSUE(0);

    float acc[2][4][4];
    #pragma unroll
    for (int a = 0; a < 2; a++)
        #pragma unroll
        for (int b = 0; b < 4; b++)
            #pragma unroll
            for (int c = 0; c < 4; c++) acc[a][b][c] = 0.f;
    float bestv[4]; int besti[4];
    #pragma unroll
    for (int s = 0; s < 4; s++) { bestv[s] = 3.0e38f; besti[s] = 0; }

    for (int gc = 0; gc < 64; gc++) {
        if (gc + 1 < 64) { ISSUE(gc + 1); CP_WAIT1(); } else { CP_WAIT0(); }
        __syncthreads();
        const float4* B4 = (gc & 1) ? smB1 : smB0;
        int ch = gc & 7;
        #pragma unroll
        for (int ksl = 0; ksl < 4; ksl++) {
            int ks = ch * 4 + ksl;
            float4 aA[2], aB[2];
            #pragma unroll
            for (int tm2 = 0; tm2 < 2; tm2++) {
                int tmg = wm * 2 + tm2;
                aA[tm2] = smA[(ks * 8 + kq) * 32 + tmg * 8 + slot];
                aB[tm2] = smA[(ks * 8 + kq + 4) * 32 + tmg * 8 + slot];
            }
            float4 bf[4];
            #pragma unroll
            for (int tn4 = 0; tn4 < 4; tn4++) {
                int tng = wn * 4 + tn4;
                bf[tn4] = B4[((ksl * 4 + kq) * 16 + tng) * 8 + slot];
            }
            #pragma unroll
            for (int tm2 = 0; tm2 < 2; tm2++) {
                uint32_t ah0 = __float_as_uint(aA[tm2].x), ah1 = __float_as_uint(aA[tm2].y);
                uint32_t ah2 = __float_as_uint(aB[tm2].x), ah3 = __float_as_uint(aB[tm2].y);
                uint32_t al0 = __float_as_uint(aA[tm2].z), al1 = __float_as_uint(aA[tm2].w);
                uint32_t al2 = __float_as_uint(aB[tm2].z), al3 = __float_as_uint(aB[tm2].w);
                #pragma unroll
                for (int tn4 = 0; tn4 < 4; tn4++) {
                    uint32_t bh0 = __float_as_uint(bf[tn4].x), bh1 = __float_as_uint(bf[tn4].y);
                    uint32_t bl0 = __float_as_uint(bf[tn4].z), bl1 = __float_as_uint(bf[tn4].w);
                    mma1688(acc[tm2][tn4], ah0, ah1, ah2, ah3, bh0, bh1);
                    mma1688(acc[tm2][tn4], ah0, ah1, ah2, ah3, bl0, bl1);
                    mma1688(acc[tm2][tn4], al0, al1, al2, al3, bh0, bh1);
                }
            }
        }
        if ((gc & 7) == 7) {
            int cg = gc >> 3;
            #pragma unroll
            for (int tm2 = 0; tm2 < 2; tm2++) {
                #pragma unroll
                for (int tn4 = 0; tn4 < 4; tn4++) {
                    int nb = cg * 128 + wn * 32 + tn4 * 8 + 2 * kq;
                    float e0v = s_en[nb], e1v = s_en[nb + 1];
                    float s00 = fmaf(-2.0f, acc[tm2][tn4][0], e0v);
                    float s01 = fmaf(-2.0f, acc[tm2][tn4][1], e1v);
                    float s10 = fmaf(-2.0f, acc[tm2][tn4][2], e0v);
                    float s11 = fmaf(-2.0f, acc[tm2][tn4][3], e1v);
                    int s0 = tm2 * 2, s1 = tm2 * 2 + 1;
                    if (s00 < bestv[s0]) { bestv[s0] = s00; besti[s0] = nb; }
                    if (s01 < bestv[s0]) { bestv[s0] = s01; besti[s0] = nb + 1; }
                    if (s10 < bestv[s1]) { bestv[s1] = s10; besti[s1] = nb; }
                    if (s11 < bestv[s1]) { bestv[s1] = s11; besti[s1] = nb + 1; }
                    acc[tm2][tn4][0] = 0.f; acc[tm2][tn4][1] = 0.f;
                    acc[tm2][tn4][2] = 0.f; acc[tm2][tn4][3] = 0.f;
                }
            }
        }
        __syncthreads();
    }
    #pragma unroll
    for (int s = 0; s < 4; s++) {
        float v = bestv[s]; int bi = besti[s];
        #pragma unroll
        for (int off = 1; off <= 2; off <<= 1) {
            float ov = __shfl_xor_sync(0xffffffffu, v, off);
            int   oi = __shfl_xor_sync(0xffffffffu, bi, off);
            if (ov < v || (ov == v && oi < bi)) { v = ov; bi = oi; }
        }
        if ((lane & 3) == 0) {
            int row = wm * 32 + (s >> 1) * 16 + (s & 1) * 8 + q;
            redv[row * 4 + wn] = v;
            redi[row * 4 + wn] = bi;
        }
    }
    __syncthreads();
    float myd2 = 0.f;
    if (tid < 64) {
        float v = redv[tid * 4]; int bi = redi[tid * 4];
        #pragma unroll
        for (int j = 1; j < 4; j++) {
            float ov = redv[tid * 4 + j]; int oi = redi[tid * 4 + j];
            if (ov < v || (ov == v && oi < bi)) { v = ov; bi = oi; }
        }
        int n = g * 64 + tid;
        g_idx[n] = bi;
        atomicAdd(&g_hist[bi], 1);
        myd2 = g_xn[n] + v;                    // ||x||^2 + (||e||^2 - 2x.e)
    }
    for (int o = 16; o > 0; o >>= 1) myd2 += __shfl_down_sync(0xffffffffu, myd2, o);
    if ((tid & 31) == 0 && wid < 2) lred[wid] = myd2;
    __syncthreads();
    if (tid == 0) atomicAdd(&g_mse, (double)(lred[0] + lred[1]));
}

// ---------------------------------------------------------------
// output: z_q_out[b,e,t] = embed[q_idx[b*T+t]][e]  (32x32 transpose)
// ---------------------------------------------------------------
__global__ void k_out(const float* __restrict__ embed, float* __restrict__ out) {
    __shared__ int   qs[32];
    __shared__ float sm[32][33];
    int b  = blockIdx.z;
    int e0 = blockIdx.y * 32;
    int t0 = blockIdx.x * 32;
    int tid = threadIdx.x;
    if (tid < 32) qs[tid] = g_idx[b * Tt + t0 + tid];
    __syncthreads();
    {
        int j = tid >> 3, gg = tid & 7;
        const float4* erow = (const float4*)(embed + (size_t)qs[j] * Ee + e0);
        float4 v = erow[gg];
        sm[j][gg * 4 + 0] = v.x; sm[j][gg * 4 + 1] = v.y;
        sm[j][gg * 4 + 2] = v.z; sm[j][gg * 4 + 3] = v.w;
    }
    __syncthreads();
    int tl = tid & 31, eb = tid >> 5;
    #pragma unroll
    for (int r = 0; r < 4; r++) {
        int el = eb + r * 8;
        out[((size_t)b * Ee + e0 + el) * Tt + t0 + tl] = sm[tl][el];
    }
}

// ---------------------------------------------------------------
// tail scalars
// ---------------------------------------------------------------
__global__ void k_tail(float* __restrict__ out) {
    __shared__ float red[32];
    int tid = threadIdx.x;                     // 1024
    float p = (float)g_hist[tid] / 65536.0f;
    float term = -p * logf(p + 1e-10f);
    for (int o = 16; o > 0; o >>= 1) term += __shfl_down_sync(0xffffffffu, term, o);
    if ((tid & 31) == 0) red[tid >> 5] = term;
    __syncthreads();
    const size_t base = (size_t)Bb * Ee * Tt;
    if (tid == 0) {
        float lp = 0.f;
        #pragma unroll
        for (int i = 0; i < 32; i++) lp += red[i];
        out[base + 0]  = (float)(1.25 * (g_mse / (double)((size_t)NTOK * Ee)));
        out[base + 17] = lp;
    }
    if (tid < 16) out[base + 1 + tid] = (float)(log(1024.0) * 4096.0);
}

// ---------------------------------------------------------------
extern "C" void kernel_launch(void* const* d_in, const int* in_sizes, int n_in,
                              void* d_out, int out_size) {
    const float* inputs = (const float*)d_in[0];   // [16, 512, 4096]
    const float* proj_w = (const float*)d_in[1];   // [256, 512]
    const float* proj_b = (const float*)d_in[2];   // [256]
    const float* embed  = (const float*)d_in[3];   // [1024, 256]
    float* out = (float*)d_out;

    cudaFuncSetAttribute(k_proj, cudaFuncAttributeMaxDynamicSharedMemorySize, PROJ_DYN);
    cudaFuncSetAttribute(k_dist, cudaFuncAttributeMaxDynamicSharedMemorySize, DIST_DYN);

    k_init<<<NE, 256>>>(embed);
    k_winit<<<Cc, 256>>>(proj_w);
    k_proj<<<NTOK / 128, 256, PROJ_DYN>>>(inputs, proj_b);
    k_dist<<<NTOK / 64, 256, DIST_DYN>>>();
    dim3 g3(Tt / 32, Ee / 32, Bb);
    k_out<<<g3, 256>>>(embed, out);
    k_tail<<<1, 1024>>>(out);
}